// round 17
// baseline (speedup 1.0000x reference)
#include <cuda_runtime.h>
#include <cuda_fp16.h>
#include <math.h>

#define NB 8
#define NS 512
#define NL 4096
#define NE 768
#define NHD 384
#define NGE 32

// ---------------------------------------------------------------------------
// Static device scratch (zero-initialized; pads are never written)
// ---------------------------------------------------------------------------
__device__ __half g_Qin[NB * NS * NE];
__device__ __half g_Kin[NB * NL * NGE];
__device__ __half g_Qh [NB * NS * NE];      // compacted Q rows per batch
__device__ __half g_Kh [NB * NL * NE];      // compacted K rows per batch
__device__ __half g_Vth[NB * NE * NL];      // V^T, compacted columns per batch
__device__ __half g_dwh[NB * NS * NL];      // compacted fp16 dw
__device__ __half g_Sch[NB * 2 * NS * NL];  // compacted fp16 masked scores
__device__ __half g_Oh [NB * NS * NE];      // full (scattered rows; zero-filled)
__device__ float  g_Part[NB * 4 * NS * NE]; // split-K=4 fp32 partials (compacted rows)
__device__ __half g_WqT[NE * NE];
__device__ __half g_WkT[NE * NGE];
__device__ __half g_WvT[NE * NGE];
__device__ __half g_WoT[NE * NE];
__device__ int g_idxq[NB * NS], g_invq[NB * NS];
__device__ int g_idxl[NB * NL], g_invl[NB * NL];
__device__ int g_nq[NB], g_nqp[NB], g_nl[NB], g_nlp[NB];
__device__ float g_lam;
__device__ int   g_mode;

#define MASKVAL (-60000.0f)

// ---------------------------------------------------------------------------
// PTX helpers
// ---------------------------------------------------------------------------
__device__ __forceinline__ void cpa16(unsigned dst, const void* src)
{
    asm volatile("cp.async.cg.shared.global [%0], [%1], 16;" :: "r"(dst), "l"(src));
}
__device__ __forceinline__ void ldm4(unsigned& r0, unsigned& r1, unsigned& r2, unsigned& r3,
                                     unsigned addr)
{
    asm volatile("ldmatrix.sync.aligned.m8n8.x4.shared.b16 {%0,%1,%2,%3}, [%4];"
                 : "=r"(r0), "=r"(r1), "=r"(r2), "=r"(r3) : "r"(addr));
}
__device__ __forceinline__ void mma16(float* d, const unsigned* a, const unsigned* b)
{
    asm volatile(
        "mma.sync.aligned.m16n8k16.row.col.f32.f16.f16.f32 "
        "{%0,%1,%2,%3}, {%4,%5,%6,%7}, {%8,%9}, {%0,%1,%2,%3};"
        : "+f"(d[0]), "+f"(d[1]), "+f"(d[2]), "+f"(d[3])
        : "r"(a[0]), "r"(a[1]), "r"(a[2]), "r"(a[3]), "r"(b[0]), "r"(b[1]));
}

__device__ __forceinline__ unsigned char read_mask(const void* p, int i, int mode)
{
    if (mode == 1) return ((const int*)p)[i] != 0;
    if (mode == 2) return ((const float*)p)[i] != 0.0f;
    return ((const unsigned char*)p)[i] != 0;
}

// ---------------------------------------------------------------------------
// prep1: block 0 = mask dtype detection, block 1 = lambda
// ---------------------------------------------------------------------------
__global__ void prep1_kernel(const unsigned int* __restrict__ kmask_w, int nwords,
                             const float* __restrict__ lq1, const float* __restrict__ lk1,
                             const float* __restrict__ lq2, const float* __restrict__ lk2)
{
    const int t = threadIdx.x;
    if (blockIdx.x == 0) {
        __shared__ int bad_i32, bad_f32, any_nz;
        if (t == 0) { bad_i32 = 0; bad_f32 = 0; any_nz = 0; }
        __syncthreads();
        for (int i = t; i < nwords; i += blockDim.x) {
            unsigned int v = kmask_w[i];
            if (v != 0u) {
                atomicOr(&any_nz, 1);
                if (v != 1u)           atomicOr(&bad_i32, 1);
                if (v != 0x3F800000u)  atomicOr(&bad_f32, 1);
            }
        }
        __syncthreads();
        if (t == 0) {
            int mode = 0;
            if (any_nz && !bad_i32)      mode = 1;
            else if (any_nz && !bad_f32) mode = 2;
            g_mode = mode;
        }
    } else {
        __shared__ float r1[256], r2[256];
        float a = 0.f, b = 0.f;
        for (int i = t; i < NHD; i += 256) { a += lq1[i] * lk1[i]; b += lq2[i] * lk2[i]; }
        r1[t] = a; r2[t] = b; __syncthreads();
        for (int s = 128; s > 0; s >>= 1) {
            if (t < s) { r1[t] += r1[t + s]; r2[t] += r2[t + s]; }
            __syncthreads();
        }
        if (t == 0) g_lam = expf(r1[0]) - expf(r2[0]) + 0.2f;
    }
}

// ---------------------------------------------------------------------------
// prep3: per-batch mask compaction scans. blocks [0,8) = l-scan, [8,16) = q-scan.
// ---------------------------------------------------------------------------
__global__ void prep3_kernel(const void* __restrict__ qmask, const void* __restrict__ kmask)
{
    __shared__ int sc[256];
    const int t = threadIdx.x;
    const int mode = g_mode;
    if (blockIdx.x < NB) {
        const int b = blockIdx.x;
        unsigned char m[16]; int cnt = 0;
#pragma unroll
        for (int k = 0; k < 16; k++) {
            m[k] = read_mask(kmask, b * NL + t * 16 + k, mode);
            cnt += m[k];
        }
        sc[t] = cnt; __syncthreads();
        for (int s = 1; s < 256; s <<= 1) {
            int v = (t >= s) ? sc[t - s] : 0;
            __syncthreads();
            sc[t] += v;
            __syncthreads();
        }
        int run = sc[t] - cnt;
        const int total = sc[255];
#pragma unroll
        for (int k = 0; k < 16; k++) {
            int l = t * 16 + k;
            if (m[k]) { g_idxl[b * NL + run] = l; g_invl[b * NL + l] = run; run++; }
            else        g_invl[b * NL + l] = -1;
        }
        if (t == 0) {
            g_nl[b] = total;
            int p = (total / 256 + 1) * 256;
            g_nlp[b] = p > NL ? NL : p;
        }
    } else {
        const int b = blockIdx.x - NB;
        unsigned char m[2]; int cnt = 0;
#pragma unroll
        for (int k = 0; k < 2; k++) {
            m[k] = read_mask(qmask, b * NS + t * 2 + k, mode);
            cnt += m[k];
        }
        sc[t] = cnt; __syncthreads();
        for (int s = 1; s < 256; s <<= 1) {
            int v = (t >= s) ? sc[t - s] : 0;
            __syncthreads();
            sc[t] += v;
            __syncthreads();
        }
        int run = sc[t] - cnt;
        const int total = sc[255];
#pragma unroll
        for (int k = 0; k < 2; k++) {
            int s = t * 2 + k;
            if (m[k]) { g_idxq[b * NS + run] = s; g_invq[b * NS + s] = run; run++; }
            else        g_invq[b * NS + s] = -1;
        }
        if (t == 0) {
            g_nq[b] = total;
            g_nqp[b] = ((total + 127) / 128) * 128;
        }
    }
}

// ---------------------------------------------------------------------------
// prep2: f2h + weight transposes + zero-fill of dw and Oh (block dispatch)
// ---------------------------------------------------------------------------
__device__ __forceinline__ void do_f2h(const float* __restrict__ in,
                                       __half* __restrict__ out, int idx, int n4)
{
    if (idx < n4) {
        float4 v = ((const float4*)in)[idx];
        ((__half2*)out)[2 * idx]     = __floats2half2_rn(v.x, v.y);
        ((__half2*)out)[2 * idx + 1] = __floats2half2_rn(v.z, v.w);
    }
}

__device__ __forceinline__ void do_transpose(const float* __restrict__ in,
                                             __half* __restrict__ out,
                                             int rows, int cols, int bx, int by)
{
    __shared__ float tile[32][33];
    const int t = threadIdx.x;
    const int x = t & 31, y = t >> 5;
    const int c0 = bx * 32, r0 = by * 32;
    for (int i = 0; i < 32; i += 8) {
        int r = r0 + y + i, c = c0 + x;
        if (r < rows && c < cols) tile[y + i][x] = in[(long)r * cols + c];
    }
    __syncthreads();
    for (int i = 0; i < 32; i += 8) {
        int r = c0 + y + i, c = r0 + x;
        if (r < cols && c < rows) out[(long)r * rows + c] = __float2half_rn(tile[x][y + i]);
    }
}

__global__ void prep2_kernel(const float* __restrict__ query, const float* __restrict__ key,
                             const float* __restrict__ Wq, const float* __restrict__ Wk,
                             const float* __restrict__ Wv, const float* __restrict__ Wout,
                             float* __restrict__ dw)
{
    const int blk = blockIdx.x;
    const int t = threadIdx.x;
    if (blk < 3072) {
        do_f2h(query, g_Qin, blk * 256 + t, NB * NS * NE / 4);
    } else if (blk < 4096) {
        do_f2h(key, g_Kin, (blk - 3072) * 256 + t, NB * NL * NGE / 4);
    } else if (blk < 4672) {
        int r = blk - 4096;
        do_transpose(Wq, g_WqT, NE, NE, r % 24, r / 24);
    } else if (blk < 4696) {
        do_transpose(Wk, g_WkT, NGE, NE, blk - 4672, 0);
    } else if (blk < 4720) {
        do_transpose(Wv, g_WvT, NGE, NE, blk - 4696, 0);
    } else if (blk < 5296) {
        int r = blk - 4720;
        do_transpose(Wout, g_WoT, NE, NE, r % 24, r / 24);
    } else if (blk < 5296 + 16384) {
        int idx = (blk - 5296) * 256 + t;          // float4 index
        ((float4*)dw)[idx] = make_float4(0.f, 0.f, 0.f, 0.f);
    } else {
        int idx = (blk - 5296 - 16384) * 256 + t;  // uint4 index (8 halves)
        ((uint4*)g_Oh)[idx] = make_uint4(0u, 0u, 0u, 0u);
    }
}

// ---------------------------------------------------------------------------
// fp16 NT GEMM core. EPI: 0 fp32 plain, 3 scores(col>=bound -> MASKVAL),
// 4 fp16 row-scatter via imap (SHIFT = per-batch row capacity log2),
// 6 Vt column-scatter via imap (imap pre-offset by batch).
// ---------------------------------------------------------------------------
#define STAGES 3
#define SMEM_OF(BKH) (STAGES * 2 * 128 * ((BKH) + 8) * 2)

template<int BKH, int EPI, int SHIFT>
__device__ __forceinline__ void gemm_h(
    const __half* __restrict__ A, const __half* __restrict__ B, void* __restrict__ Cv,
    int K, int lda, int ldb, int ldc, float alpha, int bm, int bn,
    const int* __restrict__ imap, int bound)
{
    constexpr int PITCHB   = (BKH + 8) * 2;
    constexpr int OPB      = 128 * PITCHB;
    constexpr int STGB     = 2 * OPB;
    constexpr int CPR      = BKH / 8;
    constexpr int LDITER   = BKH / 16;
    constexpr int KKS      = BKH / 16;

    extern __shared__ char smc[];
    const unsigned smb = (unsigned)__cvta_generic_to_shared(smc);

    const int tid  = threadIdx.x;
    const int lane = tid & 31;
    const int wid  = tid >> 5;
    const int wm   = wid & 3;
    const int wn   = wid >> 2;
    const int lc   = lane & 3;
    const int lr   = lane >> 2;

    const unsigned a_lane = smb + (unsigned)((wm * 32 + (lane & 15)) * PITCHB
                                             + (lane >> 4) * 16);
    const unsigned b_lane = smb + (unsigned)(OPB + (wn * 64 + (lane & 15)) * PITCHB
                                             + (lane >> 4) * 16);

    float d[2][8][4];
#pragma unroll
    for (int mt = 0; mt < 2; mt++)
#pragma unroll
        for (int nt = 0; nt < 8; nt++)
#pragma unroll
            for (int i = 0; i < 4; i++) d[mt][nt][i] = 0.f;

    const int ntile = K / BKH;

#define ISSUE_TILE(T, ST)                                                          \
    do {                                                                           \
        const int k0_ = (T) * BKH;                                                 \
        const unsigned sg_ = smb + (unsigned)(ST) * STGB;                          \
        _Pragma("unroll")                                                          \
        for (int i_ = 0; i_ < LDITER; i_++) {                                      \
            int idx_ = i_ * 256 + tid;                                             \
            int row_ = idx_ / CPR, ch_ = idx_ % CPR;                               \
            unsigned off_ = (unsigned)(row_ * PITCHB + ch_ * 16);                  \
            cpa16(sg_ + off_, A + (long)(bm + row_) * lda + k0_ + ch_ * 8);        \
            cpa16(sg_ + OPB + off_, B + (long)(bn + row_) * ldb + k0_ + ch_ * 8);  \
        }                                                                          \
    } while (0)

#pragma unroll
    for (int s = 0; s < STAGES - 1; s++) {
        if (s < ntile) ISSUE_TILE(s, s);
        asm volatile("cp.async.commit_group;");
    }

    int stq = 0;
    for (int t = 0; t < ntile; t++) {
        asm volatile("cp.async.wait_group %0;" :: "n"(STAGES - 2));
        __syncthreads();
        {
            int tp = t + STAGES - 1;
            if (tp < ntile) {
                int stp = stq + STAGES - 1; if (stp >= STAGES) stp -= STAGES;
                ISSUE_TILE(tp, stp);
            }
        }
        asm volatile("cp.async.commit_group;");

        const unsigned sgb = (unsigned)stq * STGB;
        const unsigned sa = a_lane + sgb;
        const unsigned sb = b_lane + sgb;
#pragma unroll
        for (int kk = 0; kk < KKS; kk++) {
            unsigned af[2][4];
#pragma unroll
            for (int mt = 0; mt < 2; mt++)
                ldm4(af[mt][0], af[mt][1], af[mt][2], af[mt][3],
                     sa + mt * (16 * PITCHB) + kk * 32);
#pragma unroll
            for (int nb = 0; nb < 4; nb++) {
                unsigned b0, b1, b2, b3;
                ldm4(b0, b1, b2, b3, sb + nb * (16 * PITCHB) + kk * 32);
                unsigned bf0[2] = { b0, b2 };
                unsigned bf1[2] = { b1, b3 };
                mma16(d[0][2 * nb + 0], af[0], bf0);
                mma16(d[0][2 * nb + 1], af[0], bf1);
                mma16(d[1][2 * nb + 0], af[1], bf0);
                mma16(d[1][2 * nb + 1], af[1], bf1);
            }
        }
        if (++stq == STAGES) stq = 0;
    }
#undef ISSUE_TILE

#pragma unroll
    for (int mt = 0; mt < 2; mt++) {
        const int m0 = bm + wm * 32 + mt * 16 + lr;
#pragma unroll
        for (int nt = 0; nt < 8; nt++) {
            const int n0 = bn + wn * 64 + nt * 8 + lc * 2;
            if (EPI == 3) {
                __half* Ch = (__half*)Cv;
                float v0 = (n0     < bound) ? d[mt][nt][0] : MASKVAL;
                float v1 = (n0 + 1 < bound) ? d[mt][nt][1] : MASKVAL;
                float v2 = (n0     < bound) ? d[mt][nt][2] : MASKVAL;
                float v3 = (n0 + 1 < bound) ? d[mt][nt][3] : MASKVAL;
                *(__half2*)(Ch + (long)m0 * ldc + n0)       = __floats2half2_rn(v0, v1);
                *(__half2*)(Ch + (long)(m0 + 8) * ldc + n0) = __floats2half2_rn(v2, v3);
            } else if (EPI == 4) {
                __half* Ch = (__half*)Cv;
                int iv0 = imap[m0];
                int iv1 = imap[m0 + 8];
                if (iv0 >= 0) {
                    long r = ((long)(m0 >> SHIFT) << SHIFT) + iv0;
                    *(__half2*)(Ch + r * ldc + n0) =
                        __floats2half2_rn(alpha * d[mt][nt][0], alpha * d[mt][nt][1]);
                }
                if (iv1 >= 0) {
                    long r = ((long)((m0 + 8) >> SHIFT) << SHIFT) + iv1;
                    *(__half2*)(Ch + r * ldc + n0) =
                        __floats2half2_rn(alpha * d[mt][nt][2], alpha * d[mt][nt][3]);
                }
            } else if (EPI == 6) {
                __half* Ch = (__half*)Cv;
                int iv0 = imap[n0];
                int iv1 = imap[n0 + 1];
                if (iv0 >= 0) {
                    Ch[(long)m0 * ldc + iv0]       = __float2half_rn(d[mt][nt][0]);
                    Ch[(long)(m0 + 8) * ldc + iv0] = __float2half_rn(d[mt][nt][2]);
                }
                if (iv1 >= 0) {
                    Ch[(long)m0 * ldc + iv1]       = __float2half_rn(d[mt][nt][1]);
                    Ch[(long)(m0 + 8) * ldc + iv1] = __float2half_rn(d[mt][nt][3]);
                }
            } else {
                float* C = (float*)Cv;
                float2 v01 = make_float2(alpha * d[mt][nt][0], alpha * d[mt][nt][1]);
                float2 v23 = make_float2(alpha * d[mt][nt][2], alpha * d[mt][nt][3]);
                *(float2*)(C + (long)m0 * ldc + n0)       = v01;
                *(float2*)(C + (long)(m0 + 8) * ldc + n0) = v23;
            }
        }
    }
}

// ---------------------------------------------------------------------------
// Fused projections (scattering into compacted layouts)
// ---------------------------------------------------------------------------
__global__ void __launch_bounds__(256, 2) k_proj_all()
{
    const int blk = blockIdx.x;
    if (blk < 192) {
        const float qscale = 0.051031036307982884f;   // 1/sqrt(384)
        gemm_h<64, 4, 9>(g_Qin, g_WqT, g_Qh, NE, NE, NE, NE, qscale,
                         (blk / 6) * 128, (blk % 6) * 128, g_invq, 0);
    } else if (blk < 1728) {
        const int idx = blk - 192;
        gemm_h<32, 4, 12>(g_Kin, g_WkT, g_Kh, NGE, NGE, NGE, NE, 1.0f,
                          (idx / 6) * 128, (idx % 6) * 128, g_invl, 0);
    } else {
        const int idx = blk - 1728;
        const int bz = idx / 192;
        gemm_h<32, 6, 0>(g_WvT, g_Kin + (long)bz * NL * NGE,
                         g_Vth + (long)bz * NE * NL, NGE, NGE, NGE, NL, 1.0f,
                         ((idx / 32) % 6) * 128, (idx % 32) * 128,
                         g_invl + bz * NL, 0);
    }
}

__global__ void __launch_bounds__(256, 2) k_scores_h()
{
    const int z = blockIdx.z, b = z >> 1, h = z & 1;
    const int bm = blockIdx.y * 128, bn = blockIdx.x * 128;
    if (bm >= g_nqp[b] || bn >= g_nlp[b]) return;
    gemm_h<64, 3, 0>(g_Qh + (long)b * NS * NE + h * NHD,
                     g_Kh + (long)b * NL * NE + h * NHD,
                     g_Sch + (long)z * NS * NL,
                     NHD, NE, NE, NL, 1.0f, bm, bn, nullptr, g_nl[b]);
}

__global__ void __launch_bounds__(256, 2) k_dwv_h(float* __restrict__ part)
{
    const int z = blockIdx.z, b = z >> 2, c = z & 3;
    const int bm = blockIdx.y * 128, bn = blockIdx.x * 128;
    if (bm >= g_nqp[b]) return;
    const int kq = g_nlp[b] >> 2;           // multiple of 64
    const int koff = c * kq;
    gemm_h<64, 0, 0>(g_dwh + (long)b * NS * NL + koff,
                     g_Vth + (long)b * NE * NL + koff,
                     part + (long)z * NS * NE,
                     kq, NL, NL, NE, 1.0f, bm, bn, nullptr, 0);
}

__global__ void __launch_bounds__(256, 2) k_wout_h(float* __restrict__ out)
{
    gemm_h<64, 0, 0>(g_Oh, g_WoT, out, NE, NE, NE, NE, 1.0f,
                     blockIdx.y * 128, blockIdx.x * 128, nullptr, 0);
}

// ---------------------------------------------------------------------------
// Compacted register-resident dual softmax -> differential weights.
// ---------------------------------------------------------------------------
__device__ __forceinline__ float blk_red(float v, float* sm, int t, int op)
{
#pragma unroll
    for (int o = 16; o; o >>= 1) {
        float u = __shfl_xor_sync(0xFFFFFFFFu, v, o);
        v = (op == 0) ? fmaxf(v, u) : (op == 1) ? v + u : fminf(v, u);
    }
    if ((t & 31) == 0) sm[t >> 5] = v;
    __syncthreads();
    float r = sm[0];
#pragma unroll
    for (int w = 1; w < 8; w++) {
        float u = sm[w];
        r = (op == 0) ? fmaxf(r, u) : (op == 1) ? r + u : fminf(r, u);
    }
    __syncthreads();
    return r;
}

__global__ void __launch_bounds__(256) softmax_dw_kernel(float* __restrict__ dw_out)
{
    __shared__ float sm[8];
    const int row = blockIdx.x;
    const int b = row >> 9;
    const int rc = row & (NS - 1);
    if (rc >= g_nq[b]) return;
    const int t = threadIdx.x;
    const int nlp = g_nlp[b];
    const int nlb = g_nl[b];
    const __half* r0 = g_Sch + ((long)(b * 2 + 0) * NS + rc) * NL;
    const __half* r1 = g_Sch + ((long)(b * 2 + 1) * NS + rc) * NL;

    float v0[16], v1[16];
    float m0 = -3.4e38f, m1 = -3.4e38f;
#pragma unroll
    for (int j = 0; j < 2; j++) {
        const int i = 8 * t + 2048 * j;
        if (i < nlp) {
            uint4 u0 = *(const uint4*)(r0 + i);
            uint4 u1 = *(const uint4*)(r1 + i);
            const unsigned* w0 = (const unsigned*)&u0;
            const unsigned* w1 = (const unsigned*)&u1;
#pragma unroll
            for (int k = 0; k < 4; k++) {
                float2 f0 = __half22float2(*(const __half2*)&w0[k]);
                float2 f1 = __half22float2(*(const __half2*)&w1[k]);
                v0[8 * j + 2 * k]     = f0.x; v0[8 * j + 2 * k + 1] = f0.y;
                v1[8 * j + 2 * k]     = f1.x; v1[8 * j + 2 * k + 1] = f1.y;
                m0 = fmaxf(m0, fmaxf(f0.x, f0.y));
                m1 = fmaxf(m1, fmaxf(f1.x, f1.y));
            }
        } else {
#pragma unroll
            for (int k = 0; k < 8; k++) { v0[8 * j + k] = MASKVAL; v1[8 * j + k] = MASKVAL; }
        }
    }
    m0 = blk_red(m0, sm, t, 0);
    m1 = blk_red(m1, sm, t, 0);

    float sum0 = 0.f, sum1 = 0.f;
#pragma unroll
    for (int k = 0; k < 16; k++) {
        v0[k] = expf(v0[k] - m0); sum0 += v0[k];
        v1[k] = expf(v1[k] - m1); sum1 += v1[k];
    }
    sum0 = blk_red(sum0, sm, t, 1);
    sum1 = blk_red(sum1, sm, t, 1);

    const float inv0 = 1.f / (sum0 + 1e-8f);
    const float inv1 = 1.f / (sum1 + 1e-8f);
    const float lam = g_lam;
    float mn = 3.4e38f;
#pragma unroll
    for (int k = 0; k < 16; k++) {
        v0[k] = v0[k] * inv0 - lam * (v1[k] * inv1);
        mn = fminf(mn, v0[k]);
    }
    mn = blk_red(mn, sm, t, 2);

    const int sq = g_idxq[b * NS + rc];
    const int* idxl = g_idxl + b * NL;
    float*  o  = dw_out + ((long)b * NS + sq) * NL;
    __half* oh = g_dwh  + ((long)b * NS + rc) * NL;
#pragma unroll
    for (int j = 0; j < 2; j++) {
        const int i = 8 * t + 2048 * j;
        if (i >= nlp) continue;
        float r[8];
        unsigned hh[4];
#pragma unroll
        for (int k = 0; k < 8; k++) r[k] = v0[8 * j + k] - mn + 1e-5f;
#pragma unroll
        for (int k = 0; k < 4; k++) {
            __half2 h = __floats2half2_rn(r[2 * k], r[2 * k + 1]);
            hh[k] = *(const unsigned*)&h;
        }
        *(uint4*)(oh + i) = make_uint4(hh[0], hh[1], hh[2], hh[3]);
#pragma unroll
        for (int k = 0; k < 8; k++)
            if (i + k < nlb) o[idxl[i + k]] = r[k];
    }
}

// ---------------------------------------------------------------------------
// Sum 4 partials + RMSNorm, scatter row into zero-filled Oh
// ---------------------------------------------------------------------------
__global__ void __launch_bounds__(256) rmsnorm4_kernel(const float* __restrict__ part,
                                                       __half* __restrict__ O,
                                                       const float* __restrict__ w)
{
    __shared__ float red[256];
    __shared__ float buf[NE];
    const int row = blockIdx.x;
    const int b = row >> 9, rc = row & (NS - 1);
    if (rc >= g_nq[b]) return;
    const int t = threadIdx.x;
    const long base0 = ((long)(b * 4 + 0) * NS + rc) * NE;
    const long base1 = ((long)(b * 4 + 1) * NS + rc) * NE;
    const long base2 = ((long)(b * 4 + 2) * NS + rc) * NE;
    const long base3 = ((long)(b * 4 + 3) * NS + rc) * NE;
    float ss = 0.f;
    for (int i = t; i < NE; i += 256) {
        float v = part[base0 + i] + part[base1 + i] + part[base2 + i] + part[base3 + i];
        buf[i] = v;
        ss += v * v;
    }
    red[t] = ss; __syncthreads();
    for (int st = 128; st > 0; st >>= 1) { if (t < st) red[t] += red[t + st]; __syncthreads(); }
    const float sc = (1.0f / sqrtf(red[0] / (float)NE + 1e-5f)) * 0.8f;
    const int sq = g_idxq[b * NS + rc];
    __half* o = O + ((long)b * NS + sq) * NE;
    for (int i = t; i < NE; i += 256) o[i] = __float2half_rn(buf[i] * sc * w[i]);
}

// ---------------------------------------------------------------------------
// Launch
// ---------------------------------------------------------------------------
extern "C" void kernel_launch(void* const* d_in, const int* in_sizes, int n_in,
                              void* d_out, int out_size)
{
    const float* query = (const float*)d_in[0];
    const float* key   = (const float*)d_in[1];
    const void*  qmask = d_in[2];
    const void*  kmask = d_in[3];
    const float* Wq    = (const float*)d_in[4];
    const float* Wk    = (const float*)d_in[5];
    const float* Wv    = (const float*)d_in[6];
    const float* Wout  = (const float*)d_in[7];
    const float* lq1   = (const float*)d_in[8];
    const float* lk1   = (const float*)d_in[9];
    const float* lq2   = (const float*)d_in[10];
    const float* lk2   = (const float*)d_in[11];
    const float* rms_w = (const float*)d_in[12];

    float* out = (float*)d_out;
    float* dw  = out + (long)NB * NS * NE;

    void* p;
    __half *Ohp;
    float *Partp;
    cudaGetSymbolAddress(&p, g_Oh);   Ohp   = (__half*)p;
    cudaGetSymbolAddress(&p, g_Part); Partp = (float*)p;

    const int SM64 = SMEM_OF(64);
    cudaFuncSetAttribute(k_proj_all, cudaFuncAttributeMaxDynamicSharedMemorySize, SM64);
    cudaFuncSetAttribute(k_scores_h, cudaFuncAttributeMaxDynamicSharedMemorySize, SM64);
    cudaFuncSetAttribute(k_dwv_h,    cudaFuncAttributeMaxDynamicSharedMemorySize, SM64);
    cudaFuncSetAttribute(k_wout_h,   cudaFuncAttributeMaxDynamicSharedMemorySize, SM64);

    // 0) prep: mode+lambda; compaction scans; f2h/transposes/zero-fills
    prep1_kernel<<<2, 256>>>((const unsigned int*)kmask, (NB * NL) / 4,
                             lq1, lk1, lq2, lk2);
    prep3_kernel<<<16, 256>>>(qmask, kmask);
    prep2_kernel<<<5296 + 16384 + 1536, 256>>>(query, key, Wq, Wk, Wv, Wout, dw);

    // 1) projections with compacting scatter epilogues
    k_proj_all<<<3264, 256, SM64>>>();

    // 2) masked scores on compacted dims
    k_scores_h<<<dim3(NL / 128, NS / 128, NB * 2), 256, SM64>>>();

    // 3) compacted dual softmax -> dw (scatter fp32 to d_out + compact fp16)
    softmax_dw_kernel<<<NB * NS, 256>>>(dw);

    // 4) o = dw @ V on compacted dims (split-K=4)
    k_dwv_h<<<dim3(NE / 128, NS / 128, NB * 4), 256, SM64>>>(Partp);

    // 5) reduce + RMSNorm, scatter rows into zero-filled Oh
    rmsnorm4_kernel<<<NB * NS, 256>>>(Partp, Ohp, rms_w);

    // 6) out = Oh @ Wout (full; masked rows are zero)
    k_wout_h<<<dim3(NE / 128, (NB * NS) / 128), 256, SM64>>>(out);
}